// round 12
// baseline (speedup 1.0000x reference)
#include <cuda_runtime.h>

#define ROWS 48
#define ROW_ELEMS (512 * 512)                  // 262144 elements per (b,c) row
#define CHUNKS 32
#define CHUNK_ELEMS (ROW_ELEMS / CHUNKS)       // 8192
#define THREADS 256
#define VEC_PER_THREAD (CHUNK_ELEMS / 4 / THREADS)  // 8 float4 per thread

// Per-(row,chunk) partial min/max + per-row counters. Counters start zeroed
// (static zero-init) and are reset by the last departing block of each row,
// so every graph replay sees zeros. No init kernel, no allocation.
__device__ float g_pmin[ROWS][CHUNKS];
__device__ float g_pmax[ROWS][CHUNKS];
__device__ unsigned int g_arrive[ROWS];
__device__ unsigned int g_depart[ROWS];

// Reference-exact bound: b_j = fl32( mn + fl32( d * (j/16) ) ), j/16 exact.
// Exact-rounding intrinsics block fma contraction (must match JAX bit-for-bit).
__device__ __forceinline__ float bound_j(float mn, float d, int j) {
    return __fadd_rn(mn, __fmul_rn(d, (float)j * 0.0625f));
}

__global__ void __launch_bounds__(THREADS) fused_quantize_kernel(
    const float4* __restrict__ in, float4* __restrict__ out) {
    const int row = blockIdx.y;
    const int chunk = blockIdx.x;
    const long base4 = (long)row * (ROW_ELEMS / 4) + (long)chunk * (CHUNK_ELEMS / 4);
    const int tid = threadIdx.x;
    const int lane = tid & 31;

    // ---- Phase 1: load chunk into REGISTERS (read input exactly once), reduce.
    float4 data[VEC_PER_THREAD];
#pragma unroll
    for (int k = 0; k < VEC_PER_THREAD; k++) {
        data[k] = in[base4 + k * THREADS + tid];
    }

    float mn = 3.402823466e+38f;
    float mx = -3.402823466e+38f;
#pragma unroll
    for (int k = 0; k < VEC_PER_THREAD; k++) {
        float4 v = data[k];
        mn = fminf(mn, fminf(fminf(v.x, v.y), fminf(v.z, v.w)));
        mx = fmaxf(mx, fmaxf(fmaxf(v.x, v.y), fmaxf(v.z, v.w)));
    }
#pragma unroll
    for (int o = 16; o > 0; o >>= 1) {
        mn = fminf(mn, __shfl_xor_sync(0xffffffffu, mn, o));
        mx = fmaxf(mx, __shfl_xor_sync(0xffffffffu, mx, o));
    }

    __shared__ float swmn[THREADS / 32];
    __shared__ float swmx[THREADS / 32];
    if ((tid & 31) == 0) {
        swmn[tid >> 5] = mn;
        swmx[tid >> 5] = mx;
    }
    __syncthreads();

    if (tid == 0) {
        float bmn = swmn[0], bmx = swmx[0];
#pragma unroll
        for (int w = 1; w < THREADS / 32; w++) {
            bmn = fminf(bmn, swmn[w]);
            bmx = fmaxf(bmx, swmx[w]);
        }
        g_pmin[row][chunk] = bmn;
        g_pmax[row][chunk] = bmx;
        __threadfence();                       // publish partial before arriving
        atomicAdd(&g_arrive[row], 1u);
        // Per-row spin: depends ONLY on this row's 32 blocks (launch order is
        // row-major; >=23 full rows co-resident -> earlier rows always retire).
        while (atomicAdd(&g_arrive[row], 0u) < CHUNKS) {
            __nanosleep(64);
        }
        // Departure handshake: 32nd departer resets counters for next replay.
        // depart==CHUNKS implies every block has exited its spin, so nobody
        // reads g_arrive[row] anymore.
        unsigned int t = atomicAdd(&g_depart[row], 1u);
        if (t == CHUNKS - 1) {
            g_arrive[row] = 0u;
            __threadfence();
            g_depart[row] = 0u;
        }
    }
    __syncthreads();
    __threadfence();  // acquire: order partial reads after observed arrival

    // ---- Reduce the row's 32 partials (one warp; __ldcg bypasses L1).
    __shared__ float s_mn, s_mx;
    if (tid < 32) {
        float v1 = __ldcg(&g_pmin[row][tid]);
        float v2 = __ldcg(&g_pmax[row][tid]);
#pragma unroll
        for (int o = 16; o > 0; o >>= 1) {
            v1 = fminf(v1, __shfl_xor_sync(0xffffffffu, v1, o));
            v2 = fmaxf(v2, __shfl_xor_sync(0xffffffffu, v2, o));
        }
        if (tid == 0) { s_mn = v1; s_mx = v2; }
    }
    __syncthreads();

    const float rmn = s_mn;
    const float rmx = s_mx;
    const float d = __fadd_rn(rmx, -rmn);  // rmx >= rmn

    // Degenerate test, matching float32 reference arithmetic:
    // robust_eps = 4 * FLT_EPSILON; deg = d <= robust_eps + 1e-5 * |mx|
    const float thresh = __fadd_rn(4.76837158203125e-07f, __fmul_rn(1e-5f, fabsf(rmx)));
    if (d <= thresh) {
        float4 q;
        q.x = q.y = q.z = q.w = rmn;
#pragma unroll
        for (int k = 0; k < VEC_PER_THREAD; k++) {
            out[base4 + k * THREADS + tid] = q;
        }
        return;
    }

    // ---- Phase 2: lane-replicated tables (conflict-free), quantize from regs.
    __shared__ float sb[17 * 32];  // bounds b_0..b_16 (sb[0]=mn exactly)
    __shared__ float sm[16 * 32];  // mids m_0..m_15 = fl(0.5 * fl(b_j + b_{j+1}))
    for (int s = tid; s < 17 * 32; s += THREADS) {
        sb[s] = bound_j(rmn, d, s >> 5);
    }
    for (int s = tid; s < 16 * 32; s += THREADS) {
        int j = s >> 5;
        sm[s] = __fmul_rn(0.5f, __fadd_rn(bound_j(rmn, d, j), bound_j(rmn, d, j + 1)));
    }
    __syncthreads();

    const float scale = 16.0f / d;              // estimate; fixup makes it exact
    const float bias = -rmn * scale;            // (x - mn)*scale as one FFMA

#pragma unroll
    for (int k = 0; k < VEC_PER_THREAD; k++) {
        float4 v = data[k];
        float xv[4] = {v.x, v.y, v.z, v.w};
        float qv[4];
#pragma unroll
        for (int e = 0; e < 4; e++) {
            float x = xv[e];
            int r = __float2int_rz(__fmaf_rn(x, scale, bias));
            r = min(max(r, 0), 15);
            // Both probes at the SAME r -> independent LDS, one latency hop.
            // Estimate provably within +-1 region; up/down mutually exclusive:
            //   up:   b_{r+1} <= x  (r=15/x~mx spurious fire clamped by min)
            //   down: b_r     >  x  (never fires at r=0 since sb[0]=mn <= x)
            int up = (sb[((r + 1) << 5) + lane] <= x) ? 1 : 0;
            int down = (sb[(r << 5) + lane] > x) ? 1 : 0;
            r = min(r + up - down, 15);
            qv[e] = sm[(r << 5) + lane];
        }
        float4 q;
        q.x = qv[0]; q.y = qv[1]; q.z = qv[2]; q.w = qv[3];
        out[base4 + k * THREADS + tid] = q;
    }
}

extern "C" void kernel_launch(void* const* d_in, const int* in_sizes, int n_in,
                              void* d_out, int out_size) {
    const float4* in = (const float4*)d_in[0];
    float4* out = (float4*)d_out;

    dim3 grid(CHUNKS, ROWS);
    fused_quantize_kernel<<<grid, THREADS>>>(in, out);
}

// round 14
// speedup vs baseline: 1.3994x; 1.3994x over previous
#include <cuda_runtime.h>

#define ROWS 48
#define ROW_ELEMS (512 * 512)                  // 262144 elements per (b,c) row
#define CHUNKS 32
#define CHUNK_ELEMS (ROW_ELEMS / CHUNKS)       // 8192
#define THREADS 256
#define VEC_PER_THREAD (CHUNK_ELEMS / 4 / THREADS)  // 8 float4 per thread

// Per-(row,chunk) partial min/max. Every slot is written unconditionally by
// minmax_kernel on every call -> no init kernel, no atomics, deterministic.
__device__ float g_pmin[ROWS][CHUNKS];
__device__ float g_pmax[ROWS][CHUNKS];

__global__ void __launch_bounds__(THREADS) minmax_kernel(const float4* __restrict__ in) {
    const int row = blockIdx.y;
    const int chunk = blockIdx.x;
    const long base4 = (long)row * (ROW_ELEMS / 4) + (long)chunk * (CHUNK_ELEMS / 4);
    const int tid = threadIdx.x;

    float mn = 3.402823466e+38f;
    float mx = -3.402823466e+38f;

#pragma unroll
    for (int k = 0; k < VEC_PER_THREAD; k++) {
        float4 v = in[base4 + k * THREADS + tid];
        mn = fminf(mn, fminf(fminf(v.x, v.y), fminf(v.z, v.w)));
        mx = fmaxf(mx, fmaxf(fmaxf(v.x, v.y), fmaxf(v.z, v.w)));
    }

#pragma unroll
    for (int o = 16; o > 0; o >>= 1) {
        mn = fminf(mn, __shfl_xor_sync(0xffffffffu, mn, o));
        mx = fmaxf(mx, __shfl_xor_sync(0xffffffffu, mx, o));
    }

    __shared__ float smn[THREADS / 32];
    __shared__ float smx[THREADS / 32];
    if ((tid & 31) == 0) {
        smn[tid >> 5] = mn;
        smx[tid >> 5] = mx;
    }
    __syncthreads();

    if (tid == 0) {
        float bmn = smn[0], bmx = smx[0];
#pragma unroll
        for (int w = 1; w < THREADS / 32; w++) {
            bmn = fminf(bmn, smn[w]);
            bmx = fmaxf(bmx, smx[w]);
        }
        g_pmin[row][chunk] = bmn;
        g_pmax[row][chunk] = bmx;
    }
}

// Reference-exact bound: b_j = fl32( mn + fl32( d * (j/16) ) ), j/16 exact.
// Exact-rounding intrinsics block fma contraction (must match JAX bit-for-bit).
__device__ __forceinline__ float bound_j(float mn, float d, int j) {
    return __fadd_rn(mn, __fmul_rn(d, (float)j * 0.0625f));
}
// Reference-exact mid: m_j = fl32( 0.5 * fl32( b_j + b_{j+1} ) ).
__device__ __forceinline__ float mid_j(float mn, float d, int j) {
    return __fmul_rn(0.5f, __fadd_rn(bound_j(mn, d, j), bound_j(mn, d, j + 1)));
}

__global__ void __launch_bounds__(THREADS) quantize_kernel(const float4* __restrict__ in,
                                                           float4* __restrict__ out) {
    const int row = blockIdx.y;
    const int chunk = blockIdx.x;
    const long base4 = (long)row * (ROW_ELEMS / 4) + (long)chunk * (CHUNK_ELEMS / 4);
    const int tid = threadIdx.x;
    const int lane = tid & 31;

    // One warp reduces the 32 partials; broadcast via 2 smem floats.
    __shared__ float s_mn, s_mx;
    if (tid < 32) {
        float v1 = g_pmin[row][tid];
        float v2 = g_pmax[row][tid];
#pragma unroll
        for (int o = 16; o > 0; o >>= 1) {
            v1 = fminf(v1, __shfl_xor_sync(0xffffffffu, v1, o));
            v2 = fmaxf(v2, __shfl_xor_sync(0xffffffffu, v2, o));
        }
        if (tid == 0) { s_mn = v1; s_mx = v2; }
    }
    __syncthreads();

    const float mn = s_mn;
    const float mx = s_mx;
    const float d = __fadd_rn(mx, -mn);  // mx >= mn

    // Degenerate test, matching float32 reference arithmetic:
    // robust_eps = 4 * FLT_EPSILON; deg = d <= robust_eps + 1e-5 * |mx|
    const float thresh = __fadd_rn(4.76837158203125e-07f, __fmul_rn(1e-5f, fabsf(mx)));
    if (d <= thresh) {
        float4 q;
        q.x = q.y = q.z = q.w = mn;
#pragma unroll
        for (int k = 0; k < VEC_PER_THREAD; k++) {
            out[base4 + k * THREADS + tid] = q;
        }
        return;
    }

    // Warp-register tables: lane L holds b_L (probe) and m_L (mid).
    //   b_L = bound_L for L<=15, +INF for L>=16  (idx=16 -> probe INF -> r=15)
    //   m_L = mid_L   for L<=15                  (r always in [0,15])
    // Lookup = shfl.idx — no smem, no table fill, no barrier, no addr IMADs.
    const float b_lane = (lane <= 15) ? bound_j(mn, d, lane)
                                      : __int_as_float(0x7f800000);
    const float m_lane = mid_j(mn, d, (lane <= 15) ? lane : 15);

    const float scale = 16.0f / d;
    const float bias = __fmaf_rn(-mn, scale, 0.5f);  // (x-mn)*scale + 0.5, one FFMA

#pragma unroll
    for (int k = 0; k < VEC_PER_THREAD; k++) {
        float4 v = in[base4 + k * THREADS + tid];
        float xv[4] = {v.x, v.y, v.z, v.w};
        float qv[4];
#pragma unroll
        for (int e = 0; e < 4; e++) {
            float x = xv[e];
            // idx = floor((x-mn)*scale + 0.5), clamped; provably in {r, r+1}.
            int idx = __float2int_rd(__fmaf_rn(x, scale, bias));
            idx = min(max(idx, 0), 16);
            float probe = __shfl_sync(0xffffffffu, b_lane, idx);
            // x >= b_idx -> region idx; x < b_idx -> region idx-1.
            // idx=0: probe=b_0=mn <= x always -> r=0 (no underflow).
            int r = idx - ((x < probe) ? 1 : 0);
            qv[e] = __shfl_sync(0xffffffffu, m_lane, r);
        }
        float4 q;
        q.x = qv[0]; q.y = qv[1]; q.z = qv[2]; q.w = qv[3];
        out[base4 + k * THREADS + tid] = q;
    }
}

extern "C" void kernel_launch(void* const* d_in, const int* in_sizes, int n_in,
                              void* d_out, int out_size) {
    const float4* in = (const float4*)d_in[0];
    float4* out = (float4*)d_out;

    dim3 grid(CHUNKS, ROWS);
    minmax_kernel<<<grid, THREADS>>>(in);
    quantize_kernel<<<grid, THREADS>>>(in, out);
}